// round 10
// baseline (speedup 1.0000x reference)
#include <cuda_runtime.h>
#include <float.h>
#include <limits.h>

#define B_       16
#define C_       80
#define N_       25200
#define N0_      19200
#define N1_      4800
#define N2_      1200
#define K_       25
#define NEG      (-1e30f)
#define SCORE_T  0.55f
#define NBUCK    1024
#define HB       768          // top band: bucket >= HB
#define BCAP     512
#define BSCALE   (NBUCK / (1.0f - SCORE_T))
#define NCELL    (B_ * C_)

// rn32(inter/un) > 0.5  <=>  inter > (0.5 + 2^-25) * un   (exact in double)
#define IOU_EDGE 0.500000029802322387695312500

// key: fbits(score)<<32 | (0x7FFF - n)  (u64 desc sort => score desc, n asc)
__device__ unsigned long long g_band[NCELL * BCAP];   // 5.2 MB
__device__ int   g_bandcnt[NCELL];                    // zero-init; nms resets after use
__device__ float g_kb[NCELL * K_ * 4];
__device__ float g_ks[NCELL * K_];

// ---------------------------------------------------------------------------
// Kernel A: stream all cls/conf once; append only top-band candidates.
// Warp chunk = 160 consecutive float4 (8 anchors x 80 classes). No smem.
// ---------------------------------------------------------------------------
__global__ __launch_bounds__(256) void band_scatter(
    const float* __restrict__ conf0, const float* __restrict__ cls0,
    const float* __restrict__ conf1, const float* __restrict__ cls1,
    const float* __restrict__ conf2, const float* __restrict__ cls2)
{
    const int F    = B_ * N_ * 20;                    // 8,064,000 float4 (mult of 160)
    const int gw   = (blockIdx.x * 256 + threadIdx.x) >> 5;
    const int lane = threadIdx.x & 31;
    const int nw   = (gridDim.x * 256) >> 5;

    for (int base = gw * 160; base < F; base += nw * 160) {
        float4 p[5]; float cv[5]; int nn[5], qq[5], bb[5];
        const float4* cl4a[5]; const float* cfa[5];
        #pragma unroll
        for (int j = 0; j < 5; j++) {
            int f = base + j * 32 + lane;
            int a = f / 20, q = f - a * 20;
            int b = a / N_, n = a - b * N_;
            const float* cf; const float4* cl4; int loc;
            if (n < N0_)             { cf = conf0; cl4 = (const float4*)cls0; loc = b * N0_ + n; }
            else if (n < N0_ + N1_)  { cf = conf1; cl4 = (const float4*)cls1; loc = b * N1_ + (n - N0_); }
            else                     { cf = conf2; cl4 = (const float4*)cls2; loc = b * N2_ + (n - N0_ - N1_); }
            cl4a[j] = cl4 + (size_t)loc * 20 + q;
            cfa[j]  = cf + loc;
            nn[j] = n; qq[j] = q; bb[j] = b;
        }
        #pragma unroll
        for (int j = 0; j < 5; j++) p[j] = *cl4a[j];
        #pragma unroll
        for (int j = 0; j < 5; j++) cv[j] = *cfa[j];

        #pragma unroll
        for (int j = 0; j < 5; j++) {
            #pragma unroll
            for (int e = 0; e < 4; e++) {
                float pv = (e == 0) ? p[j].x : (e == 1) ? p[j].y : (e == 2) ? p[j].z : p[j].w;
                float sc = cv[j] * pv;                 // same single f32 mul as reference
                // (sc-SCORE_T)*BSCALE >= 768.0f  <=>  bkt(sc) >= HB  (exact)
                if (sc > SCORE_T && (sc - SCORE_T) * BSCALE >= (float)HB) {
                    int cell = bb[j] * C_ + qq[j] * 4 + e;
                    int pos = atomicAdd(&g_bandcnt[cell], 1);
                    if (pos < BCAP)
                        g_band[(size_t)cell * BCAP + pos] =
                            ((unsigned long long)__float_as_uint(sc) << 32)
                          | (unsigned long long)(0x7FFF - nn[j]);
                }
            }
        }
    }
}

// ---------------------------------------------------------------------------
// shared helpers
// ---------------------------------------------------------------------------
__device__ __forceinline__ void bitonic_desc(unsigned long long* keys, int cnt, int tid)
{
    int nsort = 32;
    while (nsort < cnt) nsort <<= 1;
    for (int j = cnt + tid; j < nsort; j += 256) keys[j] = 0ull;
    __syncthreads();
    for (int k2 = 2; k2 <= nsort; k2 <<= 1) {
        for (int j = k2 >> 1; j > 0; j >>= 1) {
            for (int i = tid; i < nsort; i += 256) {
                int pp = i ^ j;
                if (pp > i) {
                    unsigned long long a = keys[i], q = keys[pp];
                    bool dir = ((i & k2) == 0);
                    if ((q > a) == dir) { keys[i] = q; keys[pp] = a; }
                }
            }
            __syncthreads();
        }
    }
}

// greedy walk over sorted band; called by warp 0 (tid<32) only.
__device__ __forceinline__ void greedy_walk(
    const unsigned long long* keys, const float4* c_box, int bandc,
    int lane, int out_base,
    float& ky1, float& kx1, float& ky2, float& kx2, float& karea, int* sh_nk)
{
    int nk = *sh_nk;
    for (int j = 0; j < bandc && nk < K_; j++) {
        unsigned long long kk = keys[j];
        if (kk == 0ull) break;
        float  sc = __uint_as_float((unsigned)(kk >> 32));
        float4 bx = c_box[j];
        float y1 = fminf(bx.x, bx.z), y2 = fmaxf(bx.x, bx.z);
        float x1 = fminf(bx.y, bx.w), x2 = fmaxf(bx.y, bx.w);
        float ar = (y2 - y1) * (x2 - x1);
        bool sup = false;
        if (lane < nk) {
            float ih = fmaxf(fminf(y2, ky2) - fmaxf(y1, ky1), 0.f);
            float iw = fmaxf(fminf(x2, kx2) - fmaxf(x1, kx1), 0.f);
            float inter = ih * iw;
            float un = ar + karea - inter;
            sup = (un > 0.f) && ((double)inter > IOU_EDGE * (double)un);
        }
        if (!__any_sync(0xffffffffu, sup)) {
            if (lane == nk) { ky1 = y1; kx1 = x1; ky2 = y2; kx2 = x2; karea = ar; }
            if (lane == 0) {
                g_ks[out_base + nk] = sc;
                ((float4*)g_kb)[out_base + nk] = bx;
            }
            nk++;
        }
    }
    if (lane == 0) *sh_nk = nk;
}

__device__ __forceinline__ float score_at(
    int b, int c, int n,
    const float* conf0, const float* cls0,
    const float* conf1, const float* cls1,
    const float* conf2, const float* cls2)
{
    const float *cf, *cl; int loc;
    if (n < N0_)             { cf = conf0; cl = cls0; loc = b * N0_ + n; }
    else if (n < N0_ + N1_)  { cf = conf1; cl = cls1; loc = b * N1_ + (n - N0_); }
    else                     { cf = conf2; cl = cls2; loc = b * N2_ + (n - N0_ - N1_); }
    return cf[loc] * cl[(size_t)loc * C_ + c];
}

// ---------------------------------------------------------------------------
// Kernel B: per-(b,c) NMS. Common path: sorted top-band walk (no dense read).
// Exact fallback: recompute-from-inputs histogram banding (rare).
// Resets g_bandcnt[cell] race-free: single reader/writer + barrier.
// ---------------------------------------------------------------------------
__global__ __launch_bounds__(256) void nms_kernel(
    const float* __restrict__ bbox0, const float* __restrict__ bbox1,
    const float* __restrict__ bbox2,
    const float* __restrict__ conf0, const float* __restrict__ cls0,
    const float* __restrict__ conf1, const float* __restrict__ cls1,
    const float* __restrict__ conf2, const float* __restrict__ cls2)
{
    __shared__ unsigned long long keys[BCAP];     // 4 KB
    __shared__ float4 c_box[BCAP];                // 8 KB
    __shared__ int    hist[NBUCK];                // 4 KB (fallback)
    __shared__ int    ct[256];
    __shared__ int    wt[8];
    __shared__ int    red[8];
    __shared__ int    sh_cnt, sh_nk, sh_lo, sh_Shi, sh_cntraw;

    const int tid  = threadIdx.x;
    const int lane = tid & 31;
    const int wrp  = tid >> 5;
    const int cell = blockIdx.x;
    const int b    = cell / C_;
    const int c    = cell - b * C_;
    const int out_base = cell * K_;

    // RACE FIX: only tid 0 touches g_bandcnt; everyone reads the shared copy
    // after the barrier. (In R9 all threads loaded it while tid 0 reset it.)
    if (tid == 0) {
        sh_cntraw = g_bandcnt[cell];
        g_bandcnt[cell] = 0;                       // reset for next graph replay
        sh_nk = 0;
    }
    __syncthreads();
    const int  cnt_raw  = sh_cntraw;
    const bool overflow = cnt_raw > BCAP;

    // kept boxes live in warp-0 registers (lane l = kept[l])
    float ky1 = 0.f, kx1 = 0.f, ky2 = 0.f, kx2 = 0.f, karea = 0.f;

    // ---- common path: sorted top-band walk
    if (!overflow && cnt_raw > 0) {
        const int bandc = cnt_raw;
        for (int i = tid; i < bandc; i += 256)
            keys[i] = g_band[(size_t)cell * BCAP + i];
        __syncthreads();
        bitonic_desc(keys, bandc, tid);
        for (int j = tid; j < bandc; j += 256) {
            int n = 0x7FFF - (int)(keys[j] & 0x7FFFull);
            const float* bb; int loc;
            if (n < N0_)             { bb = bbox0; loc = b * N0_ + n; }
            else if (n < N0_ + N1_)  { bb = bbox1; loc = b * N1_ + (n - N0_); }
            else                     { bb = bbox2; loc = b * N2_ + (n - N0_ - N1_); }
            float4 t = ((const float4*)bb)[loc];
            t.x = fmaxf(t.x, 0.f); t.y = fmaxf(t.y, 0.f);
            t.z = fmaxf(t.z, 0.f); t.w = fmaxf(t.w, 0.f);
            c_box[j] = t;
        }
        __syncthreads();
        if (tid < 32)
            greedy_walk(keys, c_box, bandc, lane, out_base, ky1, kx1, ky2, kx2, karea, &sh_nk);
        __syncthreads();
    }

    // ---- fallback: walk buckets below the band (or full restart on overflow)
    if (sh_nk < K_) {
        const int hi_start = overflow ? NBUCK : HB;
        if (overflow && tid == 0) sh_nk = 0;      // restart from scratch
        for (int i = tid; i < NBUCK; i += 256) hist[i] = 0;
        if (tid == 0) sh_Shi = 0;
        __syncthreads();

        for (int n = tid; n < N_; n += 256) {
            float sc = score_at(b, c, n, conf0, cls0, conf1, cls1, conf2, cls2);
            if (sc > SCORE_T) {
                int bkt = min((int)((sc - SCORE_T) * BSCALE), NBUCK - 1);
                if (bkt < hi_start) atomicAdd(&hist[bkt], 1);
            }
        }
        __syncthreads();

        // suffix sum: hist[i] := S[i] = sum_{j>=i} hist[j]
        {
            int h0 = hist[4 * tid], h1 = hist[4 * tid + 1],
                h2 = hist[4 * tid + 2], h3 = hist[4 * tid + 3];
            int s3 = h3, s2 = h2 + s3, s1 = h1 + s2, s0 = h0 + s1;
            ct[tid] = s0;
            __syncthreads();
            int v = ct[tid];
            #pragma unroll
            for (int off = 1; off < 32; off <<= 1) {
                int u = __shfl_down_sync(0xffffffffu, v, off);
                if (lane + off < 32) v += u;
            }
            if (lane == 0) wt[wrp] = v;
            __syncthreads();
            int addw = 0;
            #pragma unroll
            for (int w2 = 0; w2 < 8; w2++) if (w2 > wrp) addw += wt[w2];
            int T = v + addw - ct[tid];
            hist[4 * tid]     = T + s0;
            hist[4 * tid + 1] = T + s1;
            hist[4 * tid + 2] = T + s2;
            hist[4 * tid + 3] = T + s3;
        }
        __syncthreads();

        const int total = hist[0];
        int hi = hi_start;
        while (sh_nk < K_ && sh_Shi < total && hi > 0) {
            const int S_hi = sh_Shi;
            // lo = min i < hi with S[i] - S_hi <= BCAP
            int best = INT_MAX;
            #pragma unroll
            for (int j = 0; j < 4; j++) {
                int i = 4 * tid + j;
                if (i < hi && hist[i] - S_hi <= BCAP) best = min(best, i);
            }
            #pragma unroll
            for (int off = 16; off; off >>= 1)
                best = min(best, __shfl_down_sync(0xffffffffu, best, off));
            if (lane == 0) red[wrp] = best;
            __syncthreads();
            if (tid == 0) {
                int m = INT_MAX;
                #pragma unroll
                for (int w2 = 0; w2 < 8; w2++) m = min(m, red[w2]);
                sh_lo = (m >= hi) ? hi - 1 : m;
                sh_cnt = 0;
            }
            __syncthreads();
            const int lo = sh_lo;

            // extract band [lo, hi) by recomputing scores (rare, L2-hot)
            for (int n = tid; n < N_; n += 256) {
                float sc = score_at(b, c, n, conf0, cls0, conf1, cls1, conf2, cls2);
                if (sc > SCORE_T) {
                    int bkt = min((int)((sc - SCORE_T) * BSCALE), NBUCK - 1);
                    if (bkt >= lo && bkt < hi) {
                        int pos = atomicAdd(&sh_cnt, 1);
                        if (pos < BCAP)
                            keys[pos] = ((unsigned long long)__float_as_uint(sc) << 32)
                                      | (unsigned long long)(0x7FFF - n);
                    }
                }
            }
            __syncthreads();
            int bandc = min(sh_cnt, BCAP);

            if (bandc > 0) {
                bitonic_desc(keys, bandc, tid);
                for (int j = tid; j < bandc; j += 256) {
                    int n = 0x7FFF - (int)(keys[j] & 0x7FFFull);
                    const float* bb; int loc;
                    if (n < N0_)             { bb = bbox0; loc = b * N0_ + n; }
                    else if (n < N0_ + N1_)  { bb = bbox1; loc = b * N1_ + (n - N0_); }
                    else                     { bb = bbox2; loc = b * N2_ + (n - N0_ - N1_); }
                    float4 t = ((const float4*)bb)[loc];
                    t.x = fmaxf(t.x, 0.f); t.y = fmaxf(t.y, 0.f);
                    t.z = fmaxf(t.z, 0.f); t.w = fmaxf(t.w, 0.f);
                    c_box[j] = t;
                }
                __syncthreads();
                if (tid < 32)
                    greedy_walk(keys, c_box, bandc, lane, out_base, ky1, kx1, ky2, kx2, karea, &sh_nk);
            }
            if (tid == 0) sh_Shi = hist[lo];
            hi = lo;
            __syncthreads();
        }
    }

    __syncthreads();
    const int nkf = sh_nk;
    for (int kk = nkf + tid; kk < K_; kk += 256) {
        g_ks[out_base + kk] = NEG;
        ((float4*)g_kb)[out_base + kk] = make_float4(0.f, 0.f, 0.f, 0.f);
    }
}

// ---------------------------------------------------------------------------
// Kernel C: per-batch cross-class top-K via two-phase warp tournament.
// Keys (fbits(s)<<32 | (2047-i)) preserve lax.top_k's stable ordering.
// Output (f32): boxes [B,K,4] | scores [B,K] | cls [B,K] | valid [B]
// ---------------------------------------------------------------------------
__global__ __launch_bounds__(256) void topk_kernel(float* __restrict__ out)
{
    __shared__ unsigned long long stage[8 * K_];  // 200 keys
    __shared__ unsigned long long picks[K_];

    const int b    = blockIdx.x;
    const int tid  = threadIdx.x;
    const int lane = tid & 31;
    const int w    = tid >> 5;
    const int NE   = C_ * K_;                     // 2000; 8 warps x 250

    // phase 1: warp w extracts top-25 of its 250 entries (all in registers)
    unsigned long long q[8];
    #pragma unroll
    for (int s = 0; s < 8; s++) {
        int r = s * 32 + lane;
        unsigned long long k = 0ull;
        if (r < 250) {
            int i = w * 250 + r;
            float sc = g_ks[b * NE + i];
            if (sc > SCORE_T)
                k = ((unsigned long long)__float_as_uint(sc) << 32)
                  | (unsigned long long)(2047 - i);
        }
        q[s] = k;
    }
    for (int k = 0; k < K_; k++) {
        unsigned long long lb = q[0]; int ls = 0;
        #pragma unroll
        for (int s = 1; s < 8; s++) if (q[s] > lb) { lb = q[s]; ls = s; }
        unsigned long long wb = lb;
        int wi = (lane << 3) | ls;
        #pragma unroll
        for (int off = 16; off; off >>= 1) {
            unsigned long long ob = __shfl_down_sync(0xffffffffu, wb, off);
            int oi = __shfl_down_sync(0xffffffffu, wi, off);
            if (ob > wb) { wb = ob; wi = oi; }
        }
        wb = __shfl_sync(0xffffffffu, wb, 0);
        wi = __shfl_sync(0xffffffffu, wi, 0);
        if (lane == 0) stage[w * K_ + k] = wb;
        if ((wi >> 3) == lane) q[wi & 7] = 0ull;
    }
    __syncthreads();

    // phase 2: warp 0 merges the 200 staged keys
    if (w == 0) {
        unsigned long long q2[7];
        #pragma unroll
        for (int s = 0; s < 7; s++) {
            int r = s * 32 + lane;
            q2[s] = (r < 8 * K_) ? stage[r] : 0ull;
        }
        for (int k = 0; k < K_; k++) {
            unsigned long long lb = q2[0]; int ls = 0;
            #pragma unroll
            for (int s = 1; s < 7; s++) if (q2[s] > lb) { lb = q2[s]; ls = s; }
            unsigned long long wb = lb;
            int wi = (lane << 3) | ls;
            #pragma unroll
            for (int off = 16; off; off >>= 1) {
                unsigned long long ob = __shfl_down_sync(0xffffffffu, wb, off);
                int oi = __shfl_down_sync(0xffffffffu, wi, off);
                if (ob > wb) { wb = ob; wi = oi; }
            }
            wb = __shfl_sync(0xffffffffu, wb, 0);
            wi = __shfl_sync(0xffffffffu, wi, 0);
            if (lane == 0) picks[k] = wb;
            if ((wi >> 3) == lane) q2[wi & 7] = 0ull;
        }
    }
    __syncthreads();

    const int OB_scores = B_ * K_ * 4;
    const int OB_cls    = OB_scores + B_ * K_;
    const int OB_valid  = OB_cls + B_ * K_;

    if (tid < K_) {
        unsigned long long key = picks[tid];
        float s = __uint_as_float((unsigned)(key >> 32));
        bool valid = s > SCORE_T;
        int flat = 2047 - (int)(key & 0x7FFull);
        float4 bx = make_float4(0.f, 0.f, 0.f, 0.f);
        float cid = 0.f;
        if (valid) {
            bx = ((float4*)g_kb)[b * NE + flat];
            bx.x = fminf(fmaxf(bx.x, 0.f), 1.f);
            bx.y = fminf(fmaxf(bx.y, 0.f), 1.f);
            bx.z = fminf(fmaxf(bx.z, 0.f), 1.f);
            bx.w = fminf(fmaxf(bx.w, 0.f), 1.f);
            cid = (float)(flat / K_);
        }
        int o = b * K_ + tid;
        ((float4*)out)[o]  = bx;
        out[OB_scores + o] = valid ? s : 0.f;
        out[OB_cls + o]    = cid;
    }
    if (tid < 32) {
        bool v = (tid < K_) &&
                 (__uint_as_float((unsigned)(picks[tid] >> 32)) > SCORE_T);
        unsigned m = __ballot_sync(0xffffffffu, v);
        if (tid == 0) out[OB_valid + b] = (float)__popc(m);
    }
}

// ---------------------------------------------------------------------------
extern "C" void kernel_launch(void* const* d_in, const int* in_sizes, int n_in,
                              void* d_out, int out_size)
{
    const float* bbox0 = (const float*)d_in[0];
    const float* conf0 = (const float*)d_in[1];
    const float* cls0  = (const float*)d_in[2];
    const float* bbox1 = (const float*)d_in[3];
    const float* conf1 = (const float*)d_in[4];
    const float* cls1  = (const float*)d_in[5];
    const float* bbox2 = (const float*)d_in[6];
    const float* conf2 = (const float*)d_in[7];
    const float* cls2  = (const float*)d_in[8];

    band_scatter<<<1184, 256>>>(conf0, cls0, conf1, cls1, conf2, cls2);
    nms_kernel<<<NCELL, 256>>>(bbox0, bbox1, bbox2,
                               conf0, cls0, conf1, cls1, conf2, cls2);
    topk_kernel<<<B_, 256>>>((float*)d_out);
}